// round 4
// baseline (speedup 1.0000x reference)
#include <cuda_runtime.h>
#include <math.h>

// Problem constants (fixed by the reference: T=256, B=256, I=512, H=512)
#define TT 256
#define BB 256
#define KK 512           // I == H == 512, shared K for both GEMMs
#define HH 512
#define G3 1536          // 3*H, N dim and ldC for both GEMMs
#define LN_EPS 1e-5f

// Scratch (static device globals — allocation-free per harness rules)
__device__ float g_gi[(size_t)TT * BB * G3];   // (T*B, 3H) input projections, ~402 MB
__device__ float g_gh[(size_t)BB * G3];        // (B, 3H) per-step hidden projections
__device__ float g_h [(size_t)BB * HH];        // (B, H) running hidden state

// ---------------------------------------------------------------------------
// NT GEMM: C[m,n] = sum_k A[m,k] * B[n,k] + bias[n]
// A rows optionally pre-scaled by rowScale[m] (GRU mask reset).
// K = 512 fixed, ldA = ldB = 512, ldC = 1536. Tile 64x64, KT=16,
// 256 threads, 4x4 microtile, transposed smem tiles, float4 smem reads.
// ---------------------------------------------------------------------------
__global__ __launch_bounds__(256) void gemm64_nt(
    const float* __restrict__ A, const float* __restrict__ Bm,
    const float* __restrict__ bias, const float* __restrict__ rowScale,
    float* __restrict__ C)
{
    __shared__ float As[16][64];
    __shared__ float Bs[16][64];

    const int m0  = blockIdx.y * 64;
    const int n0  = blockIdx.x * 64;
    const int tid = threadIdx.x;

    // Loader mapping: each thread loads one float4 of A and one of B per K-tile.
    const int lrow = tid >> 2;         // 0..63: tile row
    const int lk   = (tid & 3) * 4;    // 0,4,8,12: k quad
    // Compute mapping: 16x16 thread grid, 4x4 outputs each.
    const int ty = tid >> 4;           // 0..15 -> rows ty*4..ty*4+3
    const int tx = tid & 15;           // 0..15 -> cols tx*4..tx*4+3

    const float rs = rowScale ? rowScale[m0 + lrow] : 1.0f;
    const float* Ap = A  + (size_t)(m0 + lrow) * KK + lk;
    const float* Bp = Bm + (size_t)(n0 + lrow) * KK + lk;

    float acc[4][4];
    #pragma unroll
    for (int i = 0; i < 4; i++)
        #pragma unroll
        for (int j = 0; j < 4; j++) acc[i][j] = 0.0f;

    for (int k0 = 0; k0 < KK; k0 += 16) {
        float4 av = *(const float4*)(Ap + k0);
        float4 bv = *(const float4*)(Bp + k0);
        av.x *= rs; av.y *= rs; av.z *= rs; av.w *= rs;
        As[lk + 0][lrow] = av.x; As[lk + 1][lrow] = av.y;
        As[lk + 2][lrow] = av.z; As[lk + 3][lrow] = av.w;
        Bs[lk + 0][lrow] = bv.x; Bs[lk + 1][lrow] = bv.y;
        Bs[lk + 2][lrow] = bv.z; Bs[lk + 3][lrow] = bv.w;
        __syncthreads();

        #pragma unroll
        for (int k = 0; k < 16; k++) {
            float4 a = *(const float4*)&As[k][ty * 4];
            float4 b = *(const float4*)&Bs[k][tx * 4];
            acc[0][0] += a.x * b.x; acc[0][1] += a.x * b.y;
            acc[0][2] += a.x * b.z; acc[0][3] += a.x * b.w;
            acc[1][0] += a.y * b.x; acc[1][1] += a.y * b.y;
            acc[1][2] += a.y * b.z; acc[1][3] += a.y * b.w;
            acc[2][0] += a.z * b.x; acc[2][1] += a.z * b.y;
            acc[2][2] += a.z * b.z; acc[2][3] += a.z * b.w;
            acc[3][0] += a.w * b.x; acc[3][1] += a.w * b.y;
            acc[3][2] += a.w * b.z; acc[3][3] += a.w * b.w;
        }
        __syncthreads();
    }

    float4 bq = make_float4(0.f, 0.f, 0.f, 0.f);
    if (bias) bq = *(const float4*)(bias + n0 + tx * 4);
    #pragma unroll
    for (int i = 0; i < 4; i++) {
        float4 o;
        o.x = acc[i][0] + bq.x; o.y = acc[i][1] + bq.y;
        o.z = acc[i][2] + bq.z; o.w = acc[i][3] + bq.w;
        *(float4*)(C + (size_t)(m0 + ty * 4 + i) * G3 + n0 + tx * 4) = o;
    }
}

// ---------------------------------------------------------------------------
// Per-step fused gates + hidden update + LayerNorm.
// One block per batch row (256 blocks x 512 threads).
// g_gh already contains h_masked @ W_hh^T + b_hh; g_gi contains x @ W_ih^T + b_ih.
// ---------------------------------------------------------------------------
__global__ __launch_bounds__(512) void gate_ln(
    int t, const float* __restrict__ masks,
    const float* __restrict__ ln_w, const float* __restrict__ ln_b,
    float* __restrict__ y)
{
    __shared__ float red1[16];
    __shared__ float red2[16];
    __shared__ float stat[2];

    const int b = blockIdx.x;
    const int j = threadIdx.x;   // 0..511

    const float m  = masks[t * BB + b];
    const float hm = g_h[(size_t)b * HH + j] * m;

    const float* gi = g_gi + ((size_t)t * BB + b) * G3;
    const float* gh = g_gh + (size_t)b * G3;

    const float pr = gi[j]          + gh[j];
    const float pz = gi[HH + j]     + gh[HH + j];
    const float r  = 1.0f / (1.0f + expf(-pr));
    const float z  = 1.0f / (1.0f + expf(-pz));
    const float n  = tanhf(gi[2 * HH + j] + r * gh[2 * HH + j]);
    const float hn = (1.0f - z) * n + z * hm;

    g_h[(size_t)b * HH + j] = hn;

    // Block reduce sum and sum of squares over H=512
    float s1 = hn, s2 = hn * hn;
    #pragma unroll
    for (int o = 16; o > 0; o >>= 1) {
        s1 += __shfl_xor_sync(0xFFFFFFFFu, s1, o);
        s2 += __shfl_xor_sync(0xFFFFFFFFu, s2, o);
    }
    const int warp = j >> 5, lane = j & 31;
    if (lane == 0) { red1[warp] = s1; red2[warp] = s2; }
    __syncthreads();
    if (warp == 0) {
        s1 = (lane < 16) ? red1[lane] : 0.0f;
        s2 = (lane < 16) ? red2[lane] : 0.0f;
        #pragma unroll
        for (int o = 8; o > 0; o >>= 1) {
            s1 += __shfl_xor_sync(0xFFFFFFFFu, s1, o);
            s2 += __shfl_xor_sync(0xFFFFFFFFu, s2, o);
        }
        if (lane == 0) {
            const float mu  = s1 * (1.0f / HH);
            const float var = s2 * (1.0f / HH) - mu * mu;
            stat[0] = mu;
            stat[1] = rsqrtf(var + LN_EPS);
        }
    }
    __syncthreads();

    const float mu = stat[0], rstd = stat[1];
    y[((size_t)t * BB + b) * HH + j] = (hn - mu) * rstd * ln_w[j] + ln_b[j];
}

// ---------------------------------------------------------------------------
// Launcher: 1 big gi GEMM, then 256 x (gh GEMM + fused gate/LN), all
// default-stream ordered so graph capture serializes them correctly.
// ---------------------------------------------------------------------------
extern "C" void kernel_launch(void* const* d_in, const int* in_sizes, int n_in,
                              void* d_out, int out_size)
{
    const float* x     = (const float*)d_in[0];   // (T,B,I)
    const float* h0    = (const float*)d_in[1];   // (1,B,H)
    const float* masks = (const float*)d_in[2];   // (T,B,1)
    const float* W_ih  = (const float*)d_in[3];   // (3H,I)
    const float* W_hh  = (const float*)d_in[4];   // (3H,H)
    const float* b_ih  = (const float*)d_in[5];   // (3H)
    const float* b_hh  = (const float*)d_in[6];   // (3H)
    const float* ln_w  = (const float*)d_in[7];   // (H)
    const float* ln_b  = (const float*)d_in[8];   // (H)

    float* y  = (float*)d_out;                       // (T,B,H)
    float* hT = y + (size_t)TT * BB * HH;            // (1,B,H)

    float *gi_p, *gh_p, *h_p;
    cudaGetSymbolAddress((void**)&gi_p, g_gi);
    cudaGetSymbolAddress((void**)&gh_p, g_gh);
    cudaGetSymbolAddress((void**)&h_p,  g_h);

    // Phase 1: gi = x @ W_ih^T + b_ih for all timesteps (fully parallel)
    gemm64_nt<<<dim3(G3 / 64, (TT * BB) / 64), 256>>>(x, W_ih, b_ih, nullptr, gi_p);

    // h <- h0
    cudaMemcpyAsync(h_p, h0, (size_t)BB * HH * sizeof(float),
                    cudaMemcpyDeviceToDevice);

    // Phase 2: sequential recurrence
    for (int t = 0; t < TT; t++) {
        // gh = (h * mask[t]) @ W_hh^T + b_hh  (mask folded into A-tile load)
        gemm64_nt<<<dim3(G3 / 64, BB / 64), 256>>>(h_p, W_hh, b_hh,
                                                   masks + (size_t)t * BB, gh_p);
        // gates + h update + LayerNorm + write y[t]
        gate_ln<<<BB, HH>>>(t, masks, ln_w, ln_b, y);
    }

    // hT output
    cudaMemcpyAsync(hT, h_p, (size_t)BB * HH * sizeof(float),
                    cudaMemcpyDeviceToDevice);
}

// round 6
// speedup vs baseline: 1.3394x; 1.3394x over previous
#include <cuda_runtime.h>
#include <math.h>

// Problem constants (T=256, B=256, I=H=512)
#define TT 256
#define BB 256
#define KK 512
#define HH 512
#define G3 1536
#define LN_EPS 1e-5f
#define PITCH 36   // smem row pitch (words): frag-load addr mod 32 == lane -> conflict-free

// Scratch (static device globals — allocation-free)
__device__ float g_gi[(size_t)TT * BB * G3];   // (T*B, 3H) input projections
__device__ float g_gh[(size_t)BB * G3];        // (B, 3H) per-step hidden proj
__device__ float g_h [(size_t)BB * HH];        // (B, H) running hidden state

// ---------------------------------------------------------------------------
// tf32 helpers
// ---------------------------------------------------------------------------
__device__ __forceinline__ unsigned f2tf32(float x) {
    unsigned r;
    asm("cvt.rna.tf32.f32 %0, %1;" : "=r"(r) : "f"(x));
    return r;
}
__device__ __forceinline__ void split_tf32(float x, unsigned& hi, unsigned& lo) {
    hi = f2tf32(x);
    lo = f2tf32(x - __uint_as_float(hi));
}
__device__ __forceinline__ void mma_tf32(float* d, const unsigned* a, const unsigned* b) {
    asm volatile(
        "mma.sync.aligned.m16n8k8.row.col.f32.tf32.tf32.f32 "
        "{%0,%1,%2,%3},{%4,%5,%6,%7},{%8,%9},{%0,%1,%2,%3};"
        : "+f"(d[0]), "+f"(d[1]), "+f"(d[2]), "+f"(d[3])
        : "r"(a[0]), "r"(a[1]), "r"(a[2]), "r"(a[3]), "r"(b[0]), "r"(b[1]));
}

// ---------------------------------------------------------------------------
// Split-tf32 NT GEMM: C[m,n] = sum_k A[m,k]*W[n,k] + bias[n]
// A rows optionally scaled by rowScale[m] (GRU mask). K=512, ldA=ldW=512.
// Block: 64x64 tile, 256 threads (8 warps as 2m x 4n, warp tile 32x16).
// k-chunk = 32, single smem buffer + register prefetch of next chunk.
// Precision: a*w ~= ahi*whi + ahi*wlo + alo*whi  (error ~2^-21).
// ---------------------------------------------------------------------------
__global__ __launch_bounds__(256) void gemm_tf32_split(
    const float* __restrict__ A, const float* __restrict__ W,
    const float* __restrict__ bias, const float* __restrict__ rowScale,
    float* __restrict__ C, int ldc)
{
    __shared__ unsigned sAh[64 * PITCH], sAl[64 * PITCH];
    __shared__ unsigned sWh[64 * PITCH], sWl[64 * PITCH];

    const int tid  = threadIdx.x;
    const int wid  = tid >> 5;
    const int lane = tid & 31;
    const int m0   = blockIdx.y * 64;
    const int n0   = blockIdx.x * 64;

    // staging map: 4 threads per row, 8 k each (two float4)
    const int srow = tid >> 2;
    const int skq  = (tid & 3) << 3;
    const float scale = rowScale ? rowScale[m0 + srow] : 1.0f;
    const float* Ap = A + (size_t)(m0 + srow) * KK + skq;
    const float* Wp = W + (size_t)(n0 + srow) * KK + skq;

    // fragment map
    const int qr = lane >> 2;             // T/4
    const int qc = lane & 3;              // T%4
    const int m_off = (wid >> 2) * 32;    // warp m offset: 0 or 32
    const int n_off = (wid & 3) * 16;     // warp n offset: 0,16,32,48

    float acc[2][2][4];
    #pragma unroll
    for (int i = 0; i < 2; i++)
        #pragma unroll
        for (int j = 0; j < 2; j++)
            #pragma unroll
            for (int c = 0; c < 4; c++) acc[i][j][c] = 0.0f;

    // prologue: load + convert + store chunk 0
    float4 av0 = *(const float4*)(Ap);
    float4 av1 = *(const float4*)(Ap + 4);
    float4 wv0 = *(const float4*)(Wp);
    float4 wv1 = *(const float4*)(Wp + 4);
    {
        const float af[8] = {av0.x*scale, av0.y*scale, av0.z*scale, av0.w*scale,
                             av1.x*scale, av1.y*scale, av1.z*scale, av1.w*scale};
        const float wf[8] = {wv0.x, wv0.y, wv0.z, wv0.w, wv1.x, wv1.y, wv1.z, wv1.w};
        #pragma unroll
        for (int i = 0; i < 8; i++) {
            unsigned h, l;
            split_tf32(af[i], h, l);
            sAh[srow * PITCH + skq + i] = h; sAl[srow * PITCH + skq + i] = l;
            split_tf32(wf[i], h, l);
            sWh[srow * PITCH + skq + i] = h; sWl[srow * PITCH + skq + i] = l;
        }
    }
    __syncthreads();

    for (int ch = 0; ch < KK / 32; ++ch) {
        // prefetch next chunk into registers (latency hidden under MMA work)
        if (ch < KK / 32 - 1) {
            const int k0 = (ch + 1) * 32;
            av0 = *(const float4*)(Ap + k0);
            av1 = *(const float4*)(Ap + k0 + 4);
            wv0 = *(const float4*)(Wp + k0);
            wv1 = *(const float4*)(Wp + k0 + 4);
        }

        // compute: 4 k8 groups on current chunk
        #pragma unroll
        for (int g = 0; g < 4; ++g) {
            const int ko = g * 8;
            unsigned ah[2][4], al[2][4];
            #pragma unroll
            for (int mt = 0; mt < 2; mt++) {
                const int rb = (m_off + mt * 16 + qr) * PITCH + ko + qc;
                ah[mt][0] = sAh[rb];                 al[mt][0] = sAl[rb];
                ah[mt][1] = sAh[rb + 8 * PITCH];     al[mt][1] = sAl[rb + 8 * PITCH];
                ah[mt][2] = sAh[rb + 4];             al[mt][2] = sAl[rb + 4];
                ah[mt][3] = sAh[rb + 8 * PITCH + 4]; al[mt][3] = sAl[rb + 8 * PITCH + 4];
            }
            unsigned bh[2][2], bl[2][2];
            #pragma unroll
            for (int nt = 0; nt < 2; nt++) {
                const int rb = (n_off + nt * 8 + qr) * PITCH + ko + qc;
                bh[nt][0] = sWh[rb];     bl[nt][0] = sWl[rb];
                bh[nt][1] = sWh[rb + 4]; bl[nt][1] = sWl[rb + 4];
            }
            #pragma unroll
            for (int mt = 0; mt < 2; mt++)
                #pragma unroll
                for (int nt = 0; nt < 2; nt++) {
                    mma_tf32(acc[mt][nt], ah[mt], bh[nt]);
                    mma_tf32(acc[mt][nt], ah[mt], bl[nt]);
                    mma_tf32(acc[mt][nt], al[mt], bh[nt]);
                }
        }
        __syncthreads();

        // store prefetched chunk
        if (ch < KK / 32 - 1) {
            const float af[8] = {av0.x*scale, av0.y*scale, av0.z*scale, av0.w*scale,
                                 av1.x*scale, av1.y*scale, av1.z*scale, av1.w*scale};
            const float wf[8] = {wv0.x, wv0.y, wv0.z, wv0.w, wv1.x, wv1.y, wv1.z, wv1.w};
            #pragma unroll
            for (int i = 0; i < 8; i++) {
                unsigned h, l;
                split_tf32(af[i], h, l);
                sAh[srow * PITCH + skq + i] = h; sAl[srow * PITCH + skq + i] = l;
                split_tf32(wf[i], h, l);
                sWh[srow * PITCH + skq + i] = h; sWl[srow * PITCH + skq + i] = l;
            }
            __syncthreads();
        }
    }

    // epilogue: c0=(qr, 2qc), c1=(qr, 2qc+1), c2=(qr+8, 2qc), c3=(qr+8, 2qc+1)
    #pragma unroll
    for (int mt = 0; mt < 2; mt++)
        #pragma unroll
        for (int nt = 0; nt < 2; nt++) {
            const int r = m0 + m_off + mt * 16 + qr;
            const int c = n0 + n_off + nt * 8 + qc * 2;
            const float bx = bias[c], by = bias[c + 1];
            float2 o0 = make_float2(acc[mt][nt][0] + bx, acc[mt][nt][1] + by);
            float2 o1 = make_float2(acc[mt][nt][2] + bx, acc[mt][nt][3] + by);
            *(float2*)(C + (size_t)r * ldc + c)       = o0;
            *(float2*)(C + (size_t)(r + 8) * ldc + c) = o1;
        }
}

// ---------------------------------------------------------------------------
// Per-step fused gates + hidden update + LayerNorm (proven in R3/R4).
// ---------------------------------------------------------------------------
__global__ __launch_bounds__(512) void gate_ln(
    int t, const float* __restrict__ masks,
    const float* __restrict__ ln_w, const float* __restrict__ ln_b,
    float* __restrict__ y)
{
    __shared__ float red1[16];
    __shared__ float red2[16];
    __shared__ float stat[2];

    const int b = blockIdx.x;
    const int j = threadIdx.x;

    const float m  = masks[t * BB + b];
    const float hm = g_h[(size_t)b * HH + j] * m;

    const float* gi = g_gi + ((size_t)t * BB + b) * G3;
    const float* gh = g_gh + (size_t)b * G3;

    const float pr = gi[j]      + gh[j];
    const float pz = gi[HH + j] + gh[HH + j];
    const float r  = 1.0f / (1.0f + expf(-pr));
    const float z  = 1.0f / (1.0f + expf(-pz));
    const float n  = tanhf(gi[2 * HH + j] + r * gh[2 * HH + j]);
    const float hn = (1.0f - z) * n + z * hm;

    g_h[(size_t)b * HH + j] = hn;

    float s1 = hn, s2 = hn * hn;
    #pragma unroll
    for (int o = 16; o > 0; o >>= 1) {
        s1 += __shfl_xor_sync(0xFFFFFFFFu, s1, o);
        s2 += __shfl_xor_sync(0xFFFFFFFFu, s2, o);
    }
    const int warp = j >> 5, lane = j & 31;
    if (lane == 0) { red1[warp] = s1; red2[warp] = s2; }
    __syncthreads();
    if (warp == 0) {
        s1 = (lane < 16) ? red1[lane] : 0.0f;
        s2 = (lane < 16) ? red2[lane] : 0.0f;
        #pragma unroll
        for (int o = 8; o > 0; o >>= 1) {
            s1 += __shfl_xor_sync(0xFFFFFFFFu, s1, o);
            s2 += __shfl_xor_sync(0xFFFFFFFFu, s2, o);
        }
        if (lane == 0) {
            const float mu  = s1 * (1.0f / HH);
            const float var = s2 * (1.0f / HH) - mu * mu;
            stat[0] = mu;
            stat[1] = rsqrtf(var + LN_EPS);
        }
    }
    __syncthreads();

    const float mu = stat[0], rstd = stat[1];
    y[((size_t)t * BB + b) * HH + j] = (hn - mu) * rstd * ln_w[j] + ln_b[j];
}

// ---------------------------------------------------------------------------
// Launcher: 1 gi GEMM + per-step (gh GEMM, gate_ln). No global barriers,
// no spin waits — deadlock-free by construction.
// ---------------------------------------------------------------------------
extern "C" void kernel_launch(void* const* d_in, const int* in_sizes, int n_in,
                              void* d_out, int out_size)
{
    const float* x     = (const float*)d_in[0];
    const float* h0    = (const float*)d_in[1];
    const float* masks = (const float*)d_in[2];
    const float* W_ih  = (const float*)d_in[3];
    const float* W_hh  = (const float*)d_in[4];
    const float* b_ih  = (const float*)d_in[5];
    const float* b_hh  = (const float*)d_in[6];
    const float* ln_w  = (const float*)d_in[7];
    const float* ln_b  = (const float*)d_in[8];

    float* y  = (float*)d_out;
    float* hT = y + (size_t)TT * BB * HH;

    float *gi_p, *gh_p, *h_p;
    cudaGetSymbolAddress((void**)&gi_p, g_gi);
    cudaGetSymbolAddress((void**)&gh_p, g_gh);
    cudaGetSymbolAddress((void**)&h_p,  g_h);

    // Phase 1: gi = x @ W_ih^T + b_ih (fully parallel)
    gemm_tf32_split<<<dim3(G3 / 64, (TT * BB) / 64), 256>>>(
        x, W_ih, b_ih, nullptr, gi_p, G3);

    // h <- h0
    cudaMemcpyAsync(h_p, h0, (size_t)BB * HH * sizeof(float),
                    cudaMemcpyDeviceToDevice);

    // Phase 2: sequential recurrence
    for (int t = 0; t < TT; t++) {
        gemm_tf32_split<<<dim3(G3 / 64, BB / 64), 256>>>(
            h_p, W_hh, b_hh, masks + (size_t)t * BB, gh_p, G3);
        gate_ln<<<BB, HH>>>(t, masks, ln_w, ln_b, y);
    }

    // hT output
    cudaMemcpyAsync(hT, h_p, (size_t)BB * HH * sizeof(float),
                    cudaMemcpyDeviceToDevice);
}

// round 7
// speedup vs baseline: 2.2629x; 1.6895x over previous
#include <cuda_runtime.h>
#include <cuda_bf16.h>
#include <math.h>

// Problem constants (T=256, B=256, I=H=512)
#define TT 256
#define BB 256
#define KK 512          // K elems per row == u32 words per split row (hi/lo pairs)
#define HH 512
#define G3 1536
#define LN_EPS 1e-5f

// Scratch (static device globals — allocation-free)
__device__ float    g_gi[(size_t)TT * BB * G3];  // (T*B, 3H) input projections
__device__ float    g_gh[(size_t)BB * G3];       // (B, 3H) per-step hidden proj
__device__ float    g_h [(size_t)BB * HH];       // (B, H) fp32 hidden state
__device__ unsigned g_xs [(size_t)TT * BB * KK]; // x split (bf16 hi/lo pair words)
__device__ unsigned g_wis[(size_t)G3 * KK];      // W_ih split
__device__ unsigned g_whs[(size_t)G3 * KK];      // W_hh split
__device__ unsigned g_hs [(size_t)BB * KK];      // h split (updated by gate_ln)

// ---------------------------------------------------------------------------
// bf16 split helpers. Layout per row: word(2i) = hi bf16x2 of elems (2i,2i+1),
// word(2i+1) = lo bf16x2. So one row of 512 elems = 512 u32 words.
// ---------------------------------------------------------------------------
__device__ __forceinline__ uint2 split2(float x, float y) {
    __nv_bfloat16 hx = __float2bfloat16(x);
    __nv_bfloat16 hy = __float2bfloat16(y);
    __nv_bfloat16 lx = __float2bfloat16(x - __bfloat162float(hx));
    __nv_bfloat16 ly = __float2bfloat16(y - __bfloat162float(hy));
    __nv_bfloat162 hp; hp.x = hx; hp.y = hy;
    __nv_bfloat162 lp; lp.x = lx; lp.y = ly;
    uint2 o;
    o.x = *reinterpret_cast<unsigned*>(&hp);
    o.y = *reinterpret_cast<unsigned*>(&lp);
    return o;
}

__global__ void split_pairs(const float* __restrict__ src,
                            unsigned* __restrict__ dst, int npairs) {
    int i = blockIdx.x * 256 + threadIdx.x;
    if (i >= npairs) return;
    float2 v = ((const float2*)src)[i];
    ((uint2*)dst)[i] = split2(v.x, v.y);
}

__device__ __forceinline__ void mma_bf16(float* d, unsigned a0, unsigned a1,
                                         unsigned a2, unsigned a3,
                                         unsigned b0, unsigned b1) {
    asm volatile(
        "mma.sync.aligned.m16n8k16.row.col.f32.bf16.bf16.f32 "
        "{%0,%1,%2,%3},{%4,%5,%6,%7},{%8,%9},{%0,%1,%2,%3};"
        : "+f"(d[0]), "+f"(d[1]), "+f"(d[2]), "+f"(d[3])
        : "r"(a0), "r"(a1), "r"(a2), "r"(a3), "r"(b0), "r"(b1));
}

// ---------------------------------------------------------------------------
// Split-bf16 NT GEMM: C[m,n] = sum_k A[m,k]*W[n,k] + bias[n]
// A, W are pre-split (hi/lo pair words). rowScale (binary mask) zeroes A rows.
// Tile MT x 64, 256 threads, 8 warps as 2m x 4n (warp tile (MT/2) x 16).
// k-chunk = 16, double-buffered smem with permuted slots:
//   hi pair j -> slot 2*(j&3)+(j>>2), lo pair j -> +8; row pitch 24 words.
//   => fragment loads are conflict-free LDS.64 (a0,a2 / a1,a3 / b0,b1 pairs).
// Precision: a*w ~ ahi*whi + ahi*wlo + alo*whi (3 bf16 MMAs, err ~2^-18).
// ---------------------------------------------------------------------------
template<int MT>
__global__ __launch_bounds__(256) void gemm_bf16s(
    const unsigned* __restrict__ A, const unsigned* __restrict__ W,
    const float* __restrict__ bias, const float* __restrict__ rowScale,
    float* __restrict__ C, int ldc)
{
    constexpr int NMT = MT / 32;
    __shared__ unsigned sA[2][MT * 24];
    __shared__ unsigned sW[2][64 * 24];

    const int tid  = threadIdx.x;
    const int wid  = tid >> 5;
    const int lane = tid & 31;
    const int qr   = lane >> 2;
    const int qc   = lane & 3;
    const int m0   = blockIdx.y * MT;
    const int n0   = blockIdx.x * 64;
    const int m_off = (wid >> 2) * (MT / 2);
    const int n_off = (wid & 3) * 16;

    // W staging: 4 threads/row, 4 words each (pairs j, j+1), j = 2*(tid&3)
    const int wrow = tid >> 2;
    const int wj   = (tid & 3) * 2;
    const int ws0  = 2 * (wj & 3) + (wj >> 2);
    const int ws1  = 2 * ((wj + 1) & 3) + ((wj + 1) >> 2);
    const unsigned* Wp = W + (size_t)(n0 + wrow) * KK + (tid & 3) * 4;

    // A staging
    const unsigned* Ap;
    int arow, as0 = 0;
    if (MT == 64) {
        arow = tid >> 2;
        Ap = A + (size_t)(m0 + arow) * KK + (tid & 3) * 4;
    } else {                       // MT == 32: 8 threads/row, 2 words (pair j)
        arow = tid >> 3;
        const int aj = tid & 7;
        as0 = 2 * (aj & 3) + (aj >> 2);
        Ap = A + (size_t)(m0 + arow) * KK + aj * 2;
    }
    const unsigned mz =
        (rowScale == nullptr || rowScale[m0 + arow] != 0.0f) ? 0xFFFFFFFFu : 0u;

    float acc[NMT][2][4];
    #pragma unroll
    for (int mt = 0; mt < NMT; mt++)
        #pragma unroll
        for (int nt = 0; nt < 2; nt++)
            #pragma unroll
            for (int c = 0; c < 4; c++) acc[mt][nt][c] = 0.0f;

    // stage chunk 0
    {
        uint4 wv = *(const uint4*)Wp;
        sW[0][wrow * 24 + ws0]     = wv.x;
        sW[0][wrow * 24 + 8 + ws0] = wv.y;
        sW[0][wrow * 24 + ws1]     = wv.z;
        sW[0][wrow * 24 + 8 + ws1] = wv.w;
        if (MT == 64) {
            uint4 av = *(const uint4*)Ap;
            sA[0][arow * 24 + ws0]     = av.x & mz;
            sA[0][arow * 24 + 8 + ws0] = av.y & mz;
            sA[0][arow * 24 + ws1]     = av.z & mz;
            sA[0][arow * 24 + 8 + ws1] = av.w & mz;
        } else {
            uint2 av = *(const uint2*)Ap;
            sA[0][arow * 24 + as0]     = av.x & mz;
            sA[0][arow * 24 + 8 + as0] = av.y & mz;
        }
    }
    __syncthreads();

    uint4 wnx, anx4; uint2 anx2;
    for (int ch = 0; ch < 32; ++ch) {
        const int cur = ch & 1;
        if (ch < 31) {
            wnx = *(const uint4*)(Wp + (ch + 1) * 16);
            if (MT == 64) anx4 = *(const uint4*)(Ap + (ch + 1) * 16);
            else          anx2 = *(const uint2*)(Ap + (ch + 1) * 16);
        }

        const unsigned* pA = sA[cur];
        const unsigned* pW = sW[cur];
        unsigned ah[NMT][4], al[NMT][4];
        #pragma unroll
        for (int mt = 0; mt < NMT; mt++) {
            const int r = m_off + mt * 16 + qr;
            uint2 h0 = *(const uint2*)(pA + r * 24 + 2 * qc);
            uint2 h1 = *(const uint2*)(pA + (r + 8) * 24 + 2 * qc);
            uint2 l0 = *(const uint2*)(pA + r * 24 + 8 + 2 * qc);
            uint2 l1 = *(const uint2*)(pA + (r + 8) * 24 + 8 + 2 * qc);
            ah[mt][0] = h0.x; ah[mt][1] = h1.x; ah[mt][2] = h0.y; ah[mt][3] = h1.y;
            al[mt][0] = l0.x; al[mt][1] = l1.x; al[mt][2] = l0.y; al[mt][3] = l1.y;
        }
        #pragma unroll
        for (int nt = 0; nt < 2; nt++) {
            const int rn = n_off + nt * 8 + qr;
            uint2 bh = *(const uint2*)(pW + rn * 24 + 2 * qc);
            uint2 bl = *(const uint2*)(pW + rn * 24 + 8 + 2 * qc);
            #pragma unroll
            for (int mt = 0; mt < NMT; mt++) {
                mma_bf16(acc[mt][nt], ah[mt][0], ah[mt][1], ah[mt][2], ah[mt][3], bh.x, bh.y);
                mma_bf16(acc[mt][nt], ah[mt][0], ah[mt][1], ah[mt][2], ah[mt][3], bl.x, bl.y);
                mma_bf16(acc[mt][nt], al[mt][0], al[mt][1], al[mt][2], al[mt][3], bh.x, bh.y);
            }
        }

        if (ch < 31) {
            const int nb = cur ^ 1;
            sW[nb][wrow * 24 + ws0]     = wnx.x;
            sW[nb][wrow * 24 + 8 + ws0] = wnx.y;
            sW[nb][wrow * 24 + ws1]     = wnx.z;
            sW[nb][wrow * 24 + 8 + ws1] = wnx.w;
            if (MT == 64) {
                sA[nb][arow * 24 + ws0]     = anx4.x & mz;
                sA[nb][arow * 24 + 8 + ws0] = anx4.y & mz;
                sA[nb][arow * 24 + ws1]     = anx4.z & mz;
                sA[nb][arow * 24 + 8 + ws1] = anx4.w & mz;
            } else {
                sA[nb][arow * 24 + as0]     = anx2.x & mz;
                sA[nb][arow * 24 + 8 + as0] = anx2.y & mz;
            }
        }
        __syncthreads();
    }

    #pragma unroll
    for (int mt = 0; mt < NMT; mt++)
        #pragma unroll
        for (int nt = 0; nt < 2; nt++) {
            const int r = m0 + m_off + mt * 16 + qr;
            const int c = n0 + n_off + nt * 8 + qc * 2;
            const float bx = bias[c], by = bias[c + 1];
            float2 o0 = make_float2(acc[mt][nt][0] + bx, acc[mt][nt][1] + by);
            float2 o1 = make_float2(acc[mt][nt][2] + bx, acc[mt][nt][3] + by);
            *(float2*)(C + (size_t)r * ldc + c)       = o0;
            *(float2*)(C + (size_t)(r + 8) * ldc + c) = o1;
        }
}

// ---------------------------------------------------------------------------
// Per-step gates + hidden update + LayerNorm. 256 threads x 2 elems.
// Also writes the split-bf16 form of h for the next step's GEMM.
// ---------------------------------------------------------------------------
__global__ __launch_bounds__(256) void gate_ln(
    int t, const float* __restrict__ masks,
    const float* __restrict__ ln_w, const float* __restrict__ ln_b,
    float* __restrict__ y)
{
    __shared__ float red1[8];
    __shared__ float red2[8];
    __shared__ float stat[2];

    const int b   = blockIdx.x;
    const int tid = threadIdx.x;
    const int j   = tid * 2;

    const float m = masks[t * BB + b];
    const float* gi = g_gi + ((size_t)t * BB + b) * G3;
    const float* gh = g_gh + (size_t)b * G3;
    float* hp = g_h + (size_t)b * HH;

    float2 hv  = *(float2*)(hp + j);
    float2 gir = *(const float2*)(gi + j);
    float2 giz = *(const float2*)(gi + HH + j);
    float2 gin = *(const float2*)(gi + 2 * HH + j);
    float2 ghr = *(const float2*)(gh + j);
    float2 ghz = *(const float2*)(gh + HH + j);
    float2 ghn = *(const float2*)(gh + 2 * HH + j);

    const float r0 = 1.f / (1.f + expf(-(gir.x + ghr.x)));
    const float r1 = 1.f / (1.f + expf(-(gir.y + ghr.y)));
    const float z0 = 1.f / (1.f + expf(-(giz.x + ghz.x)));
    const float z1 = 1.f / (1.f + expf(-(giz.y + ghz.y)));
    const float n0 = tanhf(gin.x + r0 * ghn.x);
    const float n1 = tanhf(gin.y + r1 * ghn.y);
    const float h0 = (1.f - z0) * n0 + z0 * (hv.x * m);
    const float h1 = (1.f - z1) * n1 + z1 * (hv.y * m);

    *(float2*)(hp + j) = make_float2(h0, h1);
    ((uint2*)g_hs)[(size_t)b * (HH / 2) + tid] = split2(h0, h1);

    float s1 = h0 + h1, s2 = h0 * h0 + h1 * h1;
    #pragma unroll
    for (int o = 16; o > 0; o >>= 1) {
        s1 += __shfl_xor_sync(0xFFFFFFFFu, s1, o);
        s2 += __shfl_xor_sync(0xFFFFFFFFu, s2, o);
    }
    const int warp = tid >> 5, lane = tid & 31;
    if (lane == 0) { red1[warp] = s1; red2[warp] = s2; }
    __syncthreads();
    if (warp == 0) {
        s1 = (lane < 8) ? red1[lane] : 0.0f;
        s2 = (lane < 8) ? red2[lane] : 0.0f;
        #pragma unroll
        for (int o = 4; o > 0; o >>= 1) {
            s1 += __shfl_xor_sync(0xFFFFFFFFu, s1, o);
            s2 += __shfl_xor_sync(0xFFFFFFFFu, s2, o);
        }
        if (lane == 0) {
            const float mu = s1 * (1.0f / HH);
            stat[0] = mu;
            stat[1] = rsqrtf(s2 * (1.0f / HH) - mu * mu + LN_EPS);
        }
    }
    __syncthreads();

    const float mu = stat[0], rstd = stat[1];
    float2 w = *(const float2*)(ln_w + j);
    float2 bta = *(const float2*)(ln_b + j);
    float2 o;
    o.x = (h0 - mu) * rstd * w.x + bta.x;
    o.y = (h1 - mu) * rstd * w.y + bta.y;
    *(float2*)(y + ((size_t)t * BB + b) * HH + j) = o;
}

// ---------------------------------------------------------------------------
extern "C" void kernel_launch(void* const* d_in, const int* in_sizes, int n_in,
                              void* d_out, int out_size)
{
    const float* x     = (const float*)d_in[0];
    const float* h0    = (const float*)d_in[1];
    const float* masks = (const float*)d_in[2];
    const float* W_ih  = (const float*)d_in[3];
    const float* W_hh  = (const float*)d_in[4];
    const float* b_ih  = (const float*)d_in[5];
    const float* b_hh  = (const float*)d_in[6];
    const float* ln_w  = (const float*)d_in[7];
    const float* ln_b  = (const float*)d_in[8];

    float* y  = (float*)d_out;
    float* hT = y + (size_t)TT * BB * HH;

    float *gi_p, *gh_p, *h_p;
    unsigned *xs_p, *wis_p, *whs_p, *hs_p;
    cudaGetSymbolAddress((void**)&gi_p,  g_gi);
    cudaGetSymbolAddress((void**)&gh_p,  g_gh);
    cudaGetSymbolAddress((void**)&h_p,   g_h);
    cudaGetSymbolAddress((void**)&xs_p,  g_xs);
    cudaGetSymbolAddress((void**)&wis_p, g_wis);
    cudaGetSymbolAddress((void**)&whs_p, g_whs);
    cudaGetSymbolAddress((void**)&hs_p,  g_hs);

    // Phase 0: one-time bf16 hi/lo splits
    const int npx = TT * BB * KK / 2;
    const int npw = G3 * KK / 2;
    const int nph = BB * HH / 2;
    split_pairs<<<(npx + 255) / 256, 256>>>(x,    xs_p,  npx);
    split_pairs<<<(npw + 255) / 256, 256>>>(W_ih, wis_p, npw);
    split_pairs<<<(npw + 255) / 256, 256>>>(W_hh, whs_p, npw);
    split_pairs<<<(nph + 255) / 256, 256>>>(h0,   hs_p,  nph);
    cudaMemcpyAsync(h_p, h0, (size_t)BB * HH * sizeof(float),
                    cudaMemcpyDeviceToDevice);

    // Phase 1: gi = x @ W_ih^T + b_ih (fully parallel)
    gemm_bf16s<64><<<dim3(G3 / 64, (TT * BB) / 64), 256>>>(
        xs_p, wis_p, b_ih, nullptr, gi_p, G3);

    // Phase 2: sequential recurrence (192 blocks/step covers all SMs)
    for (int t = 0; t < TT; t++) {
        gemm_bf16s<32><<<dim3(G3 / 64, BB / 32), 256>>>(
            hs_p, whs_p, b_hh, masks + (size_t)t * BB, gh_p, G3);
        gate_ln<<<BB, 256>>>(t, masks, ln_w, ln_b, y);
    }

    // hT output
    cudaMemcpyAsync(hT, h_p, (size_t)BB * HH * sizeof(float),
                    cudaMemcpyDeviceToDevice);
}